// round 1
// baseline (speedup 1.0000x reference)
#include <cuda_runtime.h>
#include <cuda_fp16.h>

#define H 1024
#define C 56
#define T 64
#define NBLK 148
#define NT 1024

// ---------------- persistent device state ----------------
__device__ __half cWih1[3 * H * 2 * H];   // [gate][j][2H], gates = i,g,o (f dropped)
__device__ __half cWih2[3 * H * 2 * H];
__device__ __half cWih3[3 * H * H];
__device__ __half cW1[H * H];
__device__ __half cW2[H * H];
__device__ __half cV1[C * H];
__device__ __half cV2[H * H];
__device__ __half cV3[H * H];

__device__ float g_s1[H], g_s2[H], g_s3[H];
__device__ float g_TD1[H], g_TD2[H];
__device__ float g_recon1[C], g_recon2[H], g_recon3[H];
__device__ float g_BU1[H], g_BU2[H];
__device__ float g_zp2[3 * H];
__device__ float g_loss0, g_loss1, g_loss2;

__device__ unsigned g_barcnt;
__device__ volatile unsigned g_bargen;

// ---------------- grid barrier (sense via generation counter) ----------------
__device__ __forceinline__ void gridbar() {
    __syncthreads();
    if (threadIdx.x == 0) {
        asm volatile("fence.acq_rel.gpu;" ::: "memory");  // release my CTA's writes
        unsigned g = g_bargen;
        unsigned a = atomicAdd(&g_barcnt, 1u);
        if (a == NBLK - 1) {
            g_barcnt = 0;
            asm volatile("fence.acq_rel.gpu;" ::: "memory");
            g_bargen = g + 1;
        } else {
            while (g_bargen == g) { }
            asm volatile("fence.acq_rel.gpu;" ::: "memory");  // acquire
        }
    }
    __syncthreads();
}

__device__ __forceinline__ float sigm(float x) { return 1.0f / (1.0f + expf(-x)); }

// warp dot: fp16 weight row (global, L2) * fp32 activation (smem). L in {1024,2048}.
template <int L>
__device__ __forceinline__ float dot_h(const __half* __restrict__ wrow,
                                       const float* __restrict__ a, int lane) {
    float acc = 0.0f;
    const uint4* wp = reinterpret_cast<const uint4*>(wrow) + lane;
#pragma unroll
    for (int it = 0; it < (L >> 8); ++it) {
        uint4 u = __ldcg(wp + it * 32);
        float4 a0 = *reinterpret_cast<const float4*>(a + it * 256 + lane * 8);
        float4 a1 = *reinterpret_cast<const float4*>(a + it * 256 + lane * 8 + 4);
        __half2 h0 = *reinterpret_cast<__half2*>(&u.x);
        __half2 h1 = *reinterpret_cast<__half2*>(&u.y);
        __half2 h2 = *reinterpret_cast<__half2*>(&u.z);
        __half2 h3 = *reinterpret_cast<__half2*>(&u.w);
        float2 f0 = __half22float2(h0), f1 = __half22float2(h1);
        float2 f2 = __half22float2(h2), f3 = __half22float2(h3);
        acc += f0.x * a0.x; acc += f0.y * a0.y;
        acc += f1.x * a0.z; acc += f1.y * a0.w;
        acc += f2.x * a1.x; acc += f2.y * a1.y;
        acc += f3.x * a1.z; acc += f3.y * a1.w;
    }
#pragma unroll
    for (int o = 16; o; o >>= 1) acc += __shfl_xor_sync(0xffffffffu, acc, o);
    return acc;
}

// smem layout (floats): act[2048] | actB[1024] | actC[1024] | actD[1024] |
//                       nTD0[64] | gbuf[32] | W0 fp16 [1024*58]
#define SM_ACT   0
#define SM_ACTB  2048
#define SM_ACTC  3072
#define SM_ACTD  4096
#define SM_NTD0  5120
#define SM_GBUF  5184
#define SM_W0F   5216                      // float index; halves from here
#define SMEM_FLOATS (SM_W0F + (H * 58) / 2)
#define SMEM_BYTES (SMEM_FLOATS * 4)

__global__ void __launch_bounds__(NT, 1) predcells_kernel(
    const float* __restrict__ x,
    const float* __restrict__ W0w, const float* __restrict__ W0b,
    const float* __restrict__ W1w, const float* __restrict__ W1b,
    const float* __restrict__ W2w, const float* __restrict__ W2b,
    const float* __restrict__ Wih1, const float* __restrict__ b1,
    const float* __restrict__ Wih2, const float* __restrict__ b2,
    const float* __restrict__ Wih3, const float* __restrict__ b3,
    const float* __restrict__ V1w, const float* __restrict__ V1b,
    const float* __restrict__ V2w, const float* __restrict__ V2b,
    const float* __restrict__ V3w, const float* __restrict__ V3b,
    const int* __restrict__ iternum, float* __restrict__ out) {
    extern __shared__ float smem[];
    float* act  = smem + SM_ACT;
    float* actB = smem + SM_ACTB;
    float* actC = smem + SM_ACTC;
    float* actD = smem + SM_ACTD;
    float* sTD0 = smem + SM_NTD0;
    float* gbuf = smem + SM_GBUF;
    __half* sW0 = reinterpret_cast<__half*>(smem + SM_W0F);

    const int tid = threadIdx.x;
    const int cta = blockIdx.x;
    const int w = tid >> 5;
    const int lane = tid & 31;

    // ---------------- phase 0: convert weights to fp16 (gate-reordered), zero carries ----
    {
        const int gt = cta * NT + tid;
        const int gs = NBLK * NT;
        for (int i = gt; i < 3 * H * 2 * H; i += gs) {
            int g = i / (H * 2 * H);
            int r = i - g * (H * 2 * H);
            int j = r >> 11;
            int k = r & 2047;
            int orow = ((g == 0) ? 0 : (g == 1) ? 2 * H : 3 * H) + j;
            cWih1[i] = __float2half(Wih1[orow * 2 * H + k]);
            cWih2[i] = __float2half(Wih2[orow * 2 * H + k]);
        }
        for (int i = gt; i < 3 * H * H; i += gs) {
            int g = i / (H * H);
            int r = i - g * (H * H);
            int j = r >> 10;
            int k = r & 1023;
            int orow = ((g == 0) ? 0 : (g == 1) ? 2 * H : 3 * H) + j;
            cWih3[i] = __float2half(Wih3[orow * H + k]);
        }
        for (int i = gt; i < H * H; i += gs) {
            cW1[i] = __float2half(W1w[i]);
            cW2[i] = __float2half(W2w[i]);
            cV2[i] = __float2half(V2w[i]);
            cV3[i] = __float2half(V3w[i]);
        }
        for (int i = gt; i < C * H; i += gs) cV1[i] = __float2half(V1w[i]);
        if (cta == 0) {
            for (int i = tid; i < H; i += NT) {
                g_s1[i] = 0.f; g_s2[i] = 0.f; g_s3[i] = 0.f;
                g_TD1[i] = 0.f; g_TD2[i] = 0.f;
                g_recon2[i] = 0.f; g_recon3[i] = 0.f;
            }
            if (tid < C) g_recon1[tid] = 0.f;
            if (tid == 0) { g_loss0 = 0.f; g_loss1 = 0.f; g_loss2 = 0.f; }
        }
        // W0 -> smem fp16, row-padded to 58 halves (bank-conflict-free)
        for (int i = tid; i < H * C; i += NT) {
            int r = i / C, c = i - r * C;
            sW0[r * 58 + c] = __float2half(W0w[i]);
        }
    }
    gridbar();

    const int nj = (cta + 6 * NBLK < H) ? 7 : 6;  // rows j = cta + jl*148
    const int jlw = w / 3, gatew = w % 3;         // LSTM warp roles (w < 21)
    const int gofs = (gatew == 0) ? 0 : (gatew == 1) ? 2 * H : 3 * H;

    for (int t = 0; t < T; ++t) {
        // ============ P1: LSTM1 z + zp2(Wih2_td@TD2) + V2@s2_prev + V3@s3_prev ============
        if (tid < C) sTD0[tid] = x[t * C + tid] - __ldcg(&g_recon1[tid]);
        act[H + tid] = __ldcg(&g_TD1[tid]);
        actB[tid]    = __ldcg(&g_TD2[tid]);
        actC[tid]    = __ldcg(&g_s2[tid]);
        actD[tid]    = __ldcg(&g_s3[tid]);
        __syncthreads();
        {   // BU0 = W0@nTD0 + b0, recomputed per-CTA from smem W0 (no L2 traffic)
            float acc = W0b[tid];
            const __half* wr = sW0 + tid * 58;
#pragma unroll 8
            for (int c = 0; c < C; ++c) acc += __half2float(wr[c]) * sTD0[c];
            act[tid] = acc;
        }
        __syncthreads();
        if (w < 21 && jlw < nj) {
            int j = cta + jlw * NBLK;
            float z1 = dot_h<2 * H>(cWih1 + (size_t)(gatew * H + j) * (2 * H), act, lane);
            float zp = dot_h<H>(cWih2 + (size_t)(gatew * H + j) * (2 * H) + H, actB, lane);
            if (lane == 0) {
                gbuf[jlw * 3 + gatew] = z1 + b1[gofs + j];
                g_zp2[gatew * H + j] = zp + b2[gofs + j];
            }
        } else if (w >= 21 && w < 28) {
            int jl = w - 21;
            if (jl < nj && t > 0) {  // at t=0 the recon carries stay zero
                int j = cta + jl * NBLK;
                float r2 = dot_h<H>(cV2 + (size_t)j * H, actC, lane);
                float r3 = dot_h<H>(cV3 + (size_t)j * H, actD, lane);
                if (lane == 0) {
                    g_recon2[j] = r2 + V2b[j];
                    g_recon3[j] = r3 + V3b[j];
                }
            }
        } else if (cta == 0 && w == 31) {
            float s = (lane < C) ? fabsf(sTD0[lane]) : 0.f;
            if (lane + 32 < C) s += fabsf(sTD0[lane + 32]);
#pragma unroll
            for (int o = 16; o; o >>= 1) s += __shfl_xor_sync(0xffffffffu, s, o);
            if (lane == 0) g_loss0 += s;
        }
        __syncthreads();
        if (tid < nj) {
            float zi = gbuf[tid * 3], zg = gbuf[tid * 3 + 1], zo = gbuf[tid * 3 + 2];
            g_s1[cta + tid * NBLK] = sigm(zo) * tanhf(sigm(zi) * tanhf(zg));
        }
        gridbar();

        // ============ P2: nTD1, BU1 = W1@nTD1, recon1 = V1@s1, loss1 ============
        {
            float s1v = __ldcg(&g_s1[tid]);
            float ntd1 = s1v - __ldcg(&g_recon2[tid]);
            act[tid] = ntd1;
            actB[tid] = s1v;
            if (cta == 0) g_TD1[tid] = ntd1;
        }
        __syncthreads();
        if (w < nj && w < 7) {
            int j = cta + w * NBLK;
            float bu = dot_h<H>(cW1 + (size_t)j * H, act, lane);
            if (lane == 0) g_BU1[j] = bu + W1b[j];
        } else if (w == 7 && cta < C) {
            float r1 = dot_h<H>(cV1 + (size_t)cta * H, actB, lane);
            if (lane == 0) g_recon1[cta] = r1 + V1b[cta];
        } else if (cta == 0 && w == 31) {
            float s = 0.f;
            for (int m = lane; m < H; m += 32) s += fabsf(act[m]);
#pragma unroll
            for (int o = 16; o; o >>= 1) s += __shfl_xor_sync(0xffffffffu, s, o);
            if (lane == 0) g_loss1 += s;
        }
        gridbar();

        // ============ P3: z2 = Wih2_s@BU1 + zp2 -> s2 ============
        act[tid] = __ldcg(&g_BU1[tid]);
        __syncthreads();
        if (w < 21 && jlw < nj) {
            int j = cta + jlw * NBLK;
            float z = dot_h<H>(cWih2 + (size_t)(gatew * H + j) * (2 * H), act, lane);
            if (lane == 0) gbuf[jlw * 3 + gatew] = z + __ldcg(&g_zp2[gatew * H + j]);
        }
        __syncthreads();
        if (tid < nj) {
            float zi = gbuf[tid * 3], zg = gbuf[tid * 3 + 1], zo = gbuf[tid * 3 + 2];
            g_s2[cta + tid * NBLK] = sigm(zo) * tanhf(sigm(zi) * tanhf(zg));
        }
        gridbar();

        // ============ P4: nTD2, BU2 = W2@nTD2, loss2 ============
        {
            float s2v = __ldcg(&g_s2[tid]);
            float ntd2 = s2v - __ldcg(&g_recon3[tid]);
            act[tid] = ntd2;
            if (cta == 0) g_TD2[tid] = ntd2;
        }
        __syncthreads();
        if (w < nj && w < 7) {
            int j = cta + w * NBLK;
            float bu = dot_h<H>(cW2 + (size_t)j * H, act, lane);
            if (lane == 0) g_BU2[j] = bu + W2b[j];
        } else if (cta == 0 && w == 31) {
            float s = 0.f;
            for (int m = lane; m < H; m += 32) s += fabsf(act[m]);
#pragma unroll
            for (int o = 16; o; o >>= 1) s += __shfl_xor_sync(0xffffffffu, s, o);
            if (lane == 0) g_loss2 += s;
        }
        gridbar();

        // ============ P5: z3 = Wih3@BU2 + b3 -> s3 ============
        act[tid] = __ldcg(&g_BU2[tid]);
        __syncthreads();
        if (w < 21 && jlw < nj) {
            int j = cta + jlw * NBLK;
            float z = dot_h<H>(cWih3 + (size_t)(gatew * H + j) * H, act, lane);
            if (lane == 0) gbuf[jlw * 3 + gatew] = z + b3[gofs + j];
        }
        __syncthreads();
        if (tid < nj) {
            float zi = gbuf[tid * 3], zg = gbuf[tid * 3 + 1], zo = gbuf[tid * 3 + 2];
            g_s3[cta + tid * NBLK] = sigm(zo) * tanhf(sigm(zi) * tanhf(zg));
        }
        gridbar();
    }

    if (cta == 0 && tid == 0) {
        float lam = (iternum[0] <= 1000) ? 1e-4f : 1e-2f;
        out[0] = g_loss0 + lam * g_loss1 + lam * lam * g_loss2;
    }
}

extern "C" void kernel_launch(void* const* d_in, const int* in_sizes, int n_in,
                              void* d_out, int out_size) {
    (void)in_sizes; (void)n_in; (void)out_size;
    const float* x    = (const float*)d_in[0];
    const float* W0w  = (const float*)d_in[1];
    const float* W0b  = (const float*)d_in[2];
    const float* W1w  = (const float*)d_in[3];
    const float* W1b  = (const float*)d_in[4];
    const float* W2w  = (const float*)d_in[5];
    const float* W2b  = (const float*)d_in[6];
    const float* Wih1 = (const float*)d_in[7];
    const float* b1   = (const float*)d_in[8];
    const float* Wih2 = (const float*)d_in[9];
    const float* b2   = (const float*)d_in[10];
    const float* Wih3 = (const float*)d_in[11];
    const float* b3   = (const float*)d_in[12];
    const float* V1w  = (const float*)d_in[13];
    const float* V1b  = (const float*)d_in[14];
    const float* V2w  = (const float*)d_in[15];
    const float* V2b  = (const float*)d_in[16];
    const float* V3w  = (const float*)d_in[17];
    const float* V3b  = (const float*)d_in[18];
    const int*   itn  = (const int*)d_in[19];

    static bool attr_set = false;
    if (!attr_set) {
        cudaFuncSetAttribute(predcells_kernel,
                             cudaFuncAttributeMaxDynamicSharedMemorySize, SMEM_BYTES);
        attr_set = true;
    }
    predcells_kernel<<<NBLK, NT, SMEM_BYTES>>>(
        x, W0w, W0b, W1w, W1b, W2w, W2b, Wih1, b1, Wih2, b2, Wih3, b3,
        V1w, V1b, V2w, V2b, V3w, V3b, itn, (float*)d_out);
}

// round 6
// speedup vs baseline: 1.0233x; 1.0233x over previous
#include <cuda_runtime.h>
#include <cuda_fp16.h>
#include <cstdint>

#define H 1024
#define C 56
#define T 64
#define NBLK 148
#define NT 1024

// ---------------- persistent device state (converted weights) ----------------
__device__ __align__(16) __half cWih1td[3 * H * H];   // [gate i/g/o][j][k] : TD half of Wih1
__device__ __align__(16) __half cWih2s [3 * H * H];   // BU half of Wih2
__device__ __align__(16) __half cWih2td[3 * H * H];   // TD half of Wih2
__device__ __align__(16) __half cWih3  [3 * H * H];
__device__ __align__(16) __half cW1[H * H], cW2[H * H], cV2[H * H], cV3[H * H];
__device__ __align__(16) __half cV1[C * H];
__device__ __align__(16) float  cM1 [3 * H * 64];     // fused Wih1_bu @ W0, rows padded to 64
__device__ __align__(16) float  cb1v[3 * H];          // b1 + Wih1_bu @ W0b (reordered)

__device__ __align__(16) float g_s1[H], g_s2[H], g_s3[H], g_BU1[H], g_BU2[H];
__device__ __align__(16) float g_TD1[H], g_TD2[H];
__device__ __align__(16) float g_r1[64], g_r2[H], g_r3[H];

__device__ unsigned g_barcnt;            // self-resetting; net zero per launch
__device__ volatile unsigned g_bargen;

// ---------------- split grid barrier (R1-proven primitives only) ----------------
__device__ __forceinline__ unsigned bar_arrive() {
    __threadfence();                      // publish this CTA's global writes
    unsigned g = g_bargen;
    unsigned a = atomicAdd(&g_barcnt, 1u);
    if (a == NBLK - 1) {
        g_barcnt = 0;
        __threadfence();
        g_bargen = g + 1;
    }
    return g;
}
__device__ __forceinline__ void bar_wait(unsigned g) {
    while (g_bargen == g) { }
    __threadfence();                      // acquire other CTAs' writes
}

__device__ __forceinline__ float sigm(float x) { return 1.0f / (1.0f + expf(-x)); }

__device__ __forceinline__ float wred(float v) {
#pragma unroll
    for (int o = 16; o; o >>= 1) v += __shfl_xor_sync(0xffffffffu, v, o);
    return v;
}

// stage CH 16-byte chunks global -> shared with plain loads/stores (warp-cooperative)
template <int CH>
__device__ __forceinline__ void stage_row(void* sdst, const void* gsrc, int lane) {
    uint4* s = (uint4*)sdst;
    const uint4* g = (const uint4*)gsrc;
#pragma unroll
    for (int i = lane; i < CH; i += 32) s[i] = __ldcg(g + i);
}

// lane-partial dot: 1024 fp16 weights (smem) x 1024 fp32 acts (smem).
// 4 iterations x 256 = exactly 1024 elements. (The 8-iteration version spanned
// 2048 elements -> OOB shared reads = the R2..R5 illegal memory access.)
__device__ __forceinline__ float dotp(const __half* __restrict__ ws,
                                      const float* __restrict__ a, int lane) {
    float acc = 0.f;
    int o = lane << 3;
#pragma unroll
    for (int it = 0; it < 4; ++it, o += 256) {
        uint4 u = *reinterpret_cast<const uint4*>(ws + o);
        float4 a0 = *reinterpret_cast<const float4*>(a + o);
        float4 a1 = *reinterpret_cast<const float4*>(a + o + 4);
        float2 f0 = __half22float2(*reinterpret_cast<__half2*>(&u.x));
        float2 f1 = __half22float2(*reinterpret_cast<__half2*>(&u.y));
        float2 f2 = __half22float2(*reinterpret_cast<__half2*>(&u.z));
        float2 f3 = __half22float2(*reinterpret_cast<__half2*>(&u.w));
        acc += f0.x * a0.x + f0.y * a0.y + f1.x * a0.z + f1.y * a0.w
             + f2.x * a1.x + f2.y * a1.y + f3.x * a1.z + f3.y * a1.w;
    }
    return acc;
}

// smem byte offsets
#define OFF_SA   0                      // 21 rows x 2048B (fp16 weight rows)
#define OFF_SB   43008                  // 21 rows x 2048B
#define OFF_SC   86016                  // 7 rows x 2048B
#define OFF_M1   100352                 // 21 rows x 256B (fp32 M1 rows)
#define OFF_ACTA 105728
#define OFF_ACTB 109824
#define OFF_ACTC 113920
#define OFF_N0   118016
#define OFF_GBUF 118272
#define OFF_ZP2  118400
#define SMEM_BYTES 118528
// phase-0 W0 scratch is fp16: H*C*2 = 114,688 B <= SMEM_BYTES.

__global__ void __launch_bounds__(NT, 1) predcells_kernel(
    const float* __restrict__ x,
    const float* __restrict__ W0w, const float* __restrict__ W0b,
    const float* __restrict__ W1w, const float* __restrict__ W1b,
    const float* __restrict__ W2w, const float* __restrict__ W2b,
    const float* __restrict__ Wih1, const float* __restrict__ b1,
    const float* __restrict__ Wih2, const float* __restrict__ b2,
    const float* __restrict__ Wih3, const float* __restrict__ b3,
    const float* __restrict__ V1w, const float* __restrict__ V1b,
    const float* __restrict__ V2w, const float* __restrict__ V2b,
    const float* __restrict__ V3w, const float* __restrict__ V3b,
    const int* __restrict__ iternum, float* __restrict__ out) {
    extern __shared__ char smem[];
    __half* sSA = (__half*)(smem + OFF_SA);
    __half* sSB = (__half*)(smem + OFF_SB);
    __half* sSC = (__half*)(smem + OFF_SC);
    float*  sM1 = (float*)(smem + OFF_M1);
    float*  actA = (float*)(smem + OFF_ACTA);
    float*  actB = (float*)(smem + OFF_ACTB);
    float*  actC = (float*)(smem + OFF_ACTC);
    float*  n0   = (float*)(smem + OFF_N0);
    float*  gbuf = (float*)(smem + OFF_GBUF);
    float*  zp2s = (float*)(smem + OFF_ZP2);

    const int tid = threadIdx.x;
    const int cta = blockIdx.x;
    const int w = tid >> 5;
    const int lane = tid & 31;
    const int nj = (cta < H - 6 * NBLK) ? 7 : 6;
    const int jlw = w / 3, gatew = w % 3;
    const int j1 = cta + jlw * NBLK;                 // row for LSTM-warp roles
    const bool lstmw = (w < 21) && (jlw < nj);
    const int gofs = (gatew == 0) ? 0 : (gatew == 1) ? 2 * H : 3 * H;
    const int jw = cta + w * NBLK;                   // row for w<7 roles
    const int row1 = gatew * H + j1;                 // reordered gate-row index
    const bool v3w = (w >= 21 && w < 28) && ((w - 21) < nj);
    const int jv3 = cta + (w - 21) * NBLK;
    const bool v2w = (w >= 7 && w < 14) && ((w - 7) < nj);
    const int jv2 = cta + (w - 7) * NBLK;

    // =================== phase 0: convert + fuse ===================
    {
        const int gt = cta * NT + tid;
        const int gs = NBLK * NT;
        for (int i = gt; i < 3 * H * H; i += gs) {
            int g = i >> 20;
            int r = i & (H * H - 1);
            int jj = r >> 10, k = r & 1023;
            int orow = ((g == 0) ? 0 : (g == 1) ? 2 * H : 3 * H) + jj;
            const float* w1r = Wih1 + (size_t)orow * (2 * H);
            const float* w2r = Wih2 + (size_t)orow * (2 * H);
            cWih1td[i] = __float2half(w1r[H + k]);
            cWih2s[i]  = __float2half(w2r[k]);
            cWih2td[i] = __float2half(w2r[H + k]);
            cWih3[i]   = __float2half(Wih3[(size_t)orow * H + k]);
        }
        for (int i = gt; i < H * H; i += gs) {
            cW1[i] = __float2half(W1w[i]);
            cW2[i] = __float2half(W2w[i]);
            cV2[i] = __float2half(V2w[i]);
            cV3[i] = __float2half(V3w[i]);
        }
        for (int i = gt; i < C * H; i += gs) cV1[i] = __float2half(V1w[i]);

        // W0 -> smem fp16 scratch (phase 0 only; MUST stay fp16 to fit SMEM_BYTES)
        __half* W0s = (__half*)smem;
        for (int i = tid; i < H * C; i += NT) W0s[i] = __float2half(W0w[i]);
        if (cta == 0) {
            for (int i = tid; i < H; i += NT) {
                g_TD1[i] = 0.f; g_TD2[i] = 0.f;
                g_r2[i] = 0.f; g_r3[i] = 0.f; g_s3[i] = 0.f;
            }
            if (tid < 64) g_r1[tid] = 0.f;
        }
        __syncthreads();

        // M1 = Wih1_bu @ W0 (fp32 accum), cb1 = b1 + Wih1_bu @ W0b
        if (lstmw) {
            const float* wrow = Wih1 + (size_t)(gofs + j1) * (2 * H);
            float acc0 = 0.f, acc1 = 0.f, accb = 0.f;
            for (int k0 = 0; k0 < H; k0 += 32) {
                float wv = wrow[k0 + lane];
                accb += wv * W0b[k0 + lane];
#pragma unroll 8
                for (int kk = 0; kk < 32; ++kk) {
                    float ww = __shfl_sync(0xffffffffu, wv, kk);
                    int k = k0 + kk;
                    acc0 += ww * __half2float(W0s[k * C + lane]);
                    float w1v = (lane < C - 32) ? __half2float(W0s[k * C + lane + 32]) : 0.f;
                    acc1 += ww * w1v;
                }
            }
            cM1[(size_t)row1 * 64 + lane] = acc0;
            if (lane < C - 32) cM1[(size_t)row1 * 64 + lane + 32] = acc1;
            float cb = wred(accb);
            if (lane == 0) cb1v[row1] = b1[gofs + j1] + cb;
        }
    }
    // full grid barrier: all conversions visible before any staging reads them
    {
        __syncthreads();
        if (tid == 0) { unsigned bg = bar_arrive(); bar_wait(bg); }
        __syncthreads();
    }

    // hoist loop-invariant biases into registers
    float r_cb1 = 0.f, r_b2 = 0.f, r_b3 = 0.f, r_w1b = 0.f, r_w2b = 0.f;
    float r_v1b = 0.f, r_v2b = 0.f, r_v3b = 0.f;
    if (lstmw) {
        r_cb1 = __ldcg(&cb1v[row1]);
        r_b2  = b2[gofs + j1];
        r_b3  = b3[gofs + j1];
    }
    if (w < 7 && w < nj) { r_w1b = W1b[jw]; r_w2b = W2b[jw]; }
    if (w == 7 && cta < C) r_v1b = V1b[cta];
    if (v2w) r_v2b = V2b[jv2];
    if (v3w) r_v3b = V3b[jv3];

    // stage P1 weights for t=0
    if (lstmw) {
        stage_row<128>(sSA + (size_t)w * 1024, cWih1td + (size_t)row1 * 1024, lane);
        stage_row<128>(sSB + (size_t)w * 1024, cWih2td + (size_t)row1 * 1024, lane);
        stage_row<14>(sM1 + w * 64, cM1 + (size_t)row1 * 64, lane);
    } else if (v3w) {
        stage_row<128>(sSC + (size_t)(w - 21) * 1024, cV3 + (size_t)jv3 * 1024, lane);
    }

    float L0 = 0.f, L1 = 0.f, L2 = 0.f;   // loss partials, live only in cta0/w31

    for (int t = 0; t < T; ++t) {
        // =========== P1: z1 -> s1 ; zp2 ; recon3 = V3 @ s3_prev ; loss0 ===========
        {
            actA[tid] = __ldcg(&g_TD1[tid]);
            actB[tid] = __ldcg(&g_TD2[tid]);
            actC[tid] = __ldcg(&g_s3[tid]);
            if (tid < 64)
                n0[tid] = (tid < C) ? (x[t * C + tid] - __ldcg(&g_r1[tid])) : 0.f;
            __syncthreads();
            if (lstmw) {
                float p = dotp(sSA + (size_t)w * 1024, actA, lane);
                const float* m = sM1 + w * 64;
                p += m[lane] * n0[lane];
                if (lane < C - 32) p += m[lane + 32] * n0[lane + 32];
                float z1 = wred(p);
                float zp = wred(dotp(sSB + (size_t)w * 1024, actB, lane));
                if (lane == 0) { gbuf[w] = z1 + r_cb1; zp2s[w] = zp + r_b2; }
            } else if (v3w) {
                if (t > 0) {
                    float r3 = wred(dotp(sSC + (size_t)(w - 21) * 1024, actC, lane));
                    if (lane == 0) __stcg(&g_r3[jv3], r3 + r_v3b);
                }
            } else if (cta == 0 && w == 31) {
                float v = fabsf(n0[lane]);
                if (lane < C - 32) v += fabsf(n0[lane + 32]);
                L0 += v;
            }
            __syncthreads();
            if (tid < nj) {
                float zi = gbuf[tid * 3], zg = gbuf[tid * 3 + 1], zo = gbuf[tid * 3 + 2];
                __stcg(&g_s1[cta + tid * NBLK], sigm(zo) * tanhf(sigm(zi) * tanhf(zg)));
            }
            __syncthreads();
            unsigned bg; if (tid == 0) bg = bar_arrive();
            if (w < 7 && w < nj)
                stage_row<128>(sSA + (size_t)w * 1024, cW1 + (size_t)jw * 1024, lane);
            else if (w == 7 && cta < C)
                stage_row<128>(sSA + (size_t)7 * 1024, cV1 + (size_t)cta * 1024, lane);
            if (tid == 0) bar_wait(bg);
            __syncthreads();
        }
        // =========== P2: nTD1 ; BU1 = W1@nTD1 ; recon1 = V1@s1 ; loss1 ===========
        {
            float s1v = __ldcg(&g_s1[tid]);
            float ntd1 = s1v - __ldcg(&g_r2[tid]);
            actA[tid] = ntd1; actB[tid] = s1v;
            if (cta == 0) __stcg(&g_TD1[tid], ntd1);
            __syncthreads();
            if (w < 7 && w < nj) {
                float bu = wred(dotp(sSA + (size_t)w * 1024, actA, lane));
                if (lane == 0) __stcg(&g_BU1[jw], bu + r_w1b);
            } else if (w == 7 && cta < C) {
                float r1 = wred(dotp(sSA + (size_t)7 * 1024, actB, lane));
                if (lane == 0) __stcg(&g_r1[cta], r1 + r_v1b);
            } else if (cta == 0 && w == 31) {
                float v = 0.f;
                for (int m = lane; m < H; m += 32) v += fabsf(actA[m]);
                L1 += v;
            }
            __syncthreads();
            unsigned bg; if (tid == 0) bg = bar_arrive();
            if (lstmw)
                stage_row<128>(sSA + (size_t)w * 1024, cWih2s + (size_t)row1 * 1024, lane);
            if (tid == 0) bar_wait(bg);
            __syncthreads();
        }
        // =========== P3: z2 = Wih2_s@BU1 + zp2 -> s2 ===========
        {
            actA[tid] = __ldcg(&g_BU1[tid]);
            __syncthreads();
            if (lstmw) {
                float z = wred(dotp(sSA + (size_t)w * 1024, actA, lane));
                if (lane == 0) gbuf[w] = z + zp2s[w];
            }
            __syncthreads();
            if (tid < nj) {
                float zi = gbuf[tid * 3], zg = gbuf[tid * 3 + 1], zo = gbuf[tid * 3 + 2];
                __stcg(&g_s2[cta + tid * NBLK], sigm(zo) * tanhf(sigm(zi) * tanhf(zg)));
            }
            __syncthreads();
            unsigned bg; if (tid == 0) bg = bar_arrive();
            if (w < 7 && w < nj)
                stage_row<128>(sSA + (size_t)w * 1024, cW2 + (size_t)jw * 1024, lane);
            else if (v2w)
                stage_row<128>(sSA + (size_t)w * 1024, cV2 + (size_t)jv2 * 1024, lane);
            if (tid == 0) bar_wait(bg);
            __syncthreads();
        }
        // =========== P4: nTD2 ; BU2 = W2@nTD2 ; recon2 = V2@s2 ; loss2 ===========
        {
            float s2v = __ldcg(&g_s2[tid]);
            float ntd2 = s2v - __ldcg(&g_r3[tid]);
            actA[tid] = ntd2; actB[tid] = s2v;
            if (cta == 0) __stcg(&g_TD2[tid], ntd2);
            __syncthreads();
            if (w < 7 && w < nj) {
                float bu = wred(dotp(sSA + (size_t)w * 1024, actA, lane));
                if (lane == 0) __stcg(&g_BU2[jw], bu + r_w2b);
            } else if (v2w) {
                float r2 = wred(dotp(sSA + (size_t)w * 1024, actB, lane));
                if (lane == 0) __stcg(&g_r2[jv2], r2 + r_v2b);
            } else if (cta == 0 && w == 31) {
                float v = 0.f;
                for (int m = lane; m < H; m += 32) v += fabsf(actA[m]);
                L2 += v;
            }
            __syncthreads();
            unsigned bg; if (tid == 0) bg = bar_arrive();
            if (lstmw)
                stage_row<128>(sSA + (size_t)w * 1024, cWih3 + (size_t)row1 * 1024, lane);
            if (tid == 0) bar_wait(bg);
            __syncthreads();
        }
        // =========== P5: z3 = Wih3@BU2 + b3 -> s3 ===========
        {
            actA[tid] = __ldcg(&g_BU2[tid]);
            __syncthreads();
            if (lstmw) {
                float z = wred(dotp(sSA + (size_t)w * 1024, actA, lane));
                if (lane == 0) gbuf[w] = z + r_b3;
            }
            __syncthreads();
            if (tid < nj) {
                float zi = gbuf[tid * 3], zg = gbuf[tid * 3 + 1], zo = gbuf[tid * 3 + 2];
                __stcg(&g_s3[cta + tid * NBLK], sigm(zo) * tanhf(sigm(zi) * tanhf(zg)));
            }
            __syncthreads();
            unsigned bg; if (tid == 0) bg = bar_arrive();
            if (t < T - 1) {   // stage next step's P1
                if (lstmw) {
                    stage_row<128>(sSA + (size_t)w * 1024, cWih1td + (size_t)row1 * 1024, lane);
                    stage_row<128>(sSB + (size_t)w * 1024, cWih2td + (size_t)row1 * 1024, lane);
                    stage_row<14>(sM1 + w * 64, cM1 + (size_t)row1 * 64, lane);
                } else if (v3w) {
                    stage_row<128>(sSC + (size_t)(w - 21) * 1024, cV3 + (size_t)jv3 * 1024, lane);
                }
            }
            if (tid == 0) bar_wait(bg);
            __syncthreads();
        }
    }

    if (cta == 0 && w == 31) {
        float l0 = wred(L0), l1 = wred(L1), l2 = wred(L2);
        if (lane == 0) {
            float lam = (iternum[0] <= 1000) ? 1e-4f : 1e-2f;
            out[0] = l0 + lam * l1 + lam * lam * l2;
        }
    }
}

extern "C" void kernel_launch(void* const* d_in, const int* in_sizes, int n_in,
                              void* d_out, int out_size) {
    (void)in_sizes; (void)n_in; (void)out_size;
    const float* x    = (const float*)d_in[0];
    const float* W0w  = (const float*)d_in[1];
    const float* W0b  = (const float*)d_in[2];
    const float* W1w  = (const float*)d_in[3];
    const float* W1b  = (const float*)d_in[4];
    const float* W2w  = (const float*)d_in[5];
    const float* W2b  = (const float*)d_in[6];
    const float* Wih1 = (const float*)d_in[7];
    const float* b1   = (const float*)d_in[8];
    const float* Wih2 = (const float*)d_in[9];
    const float* b2   = (const float*)d_in[10];
    const float* Wih3 = (const float*)d_in[11];
    const float* b3   = (const float*)d_in[12];
    const float* V1w  = (const float*)d_in[13];
    const float* V1b  = (const float*)d_in[14];
    const float* V2w  = (const float*)d_in[15];
    const float* V2b  = (const float*)d_in[16];
    const float* V3w  = (const float*)d_in[17];
    const float* V3b  = (const float*)d_in[18];
    const int*   itn  = (const int*)d_in[19];

    static bool attr_set = false;
    if (!attr_set) {
        cudaFuncSetAttribute(predcells_kernel,
                             cudaFuncAttributeMaxDynamicSharedMemorySize, SMEM_BYTES);
        attr_set = true;
    }
    predcells_kernel<<<NBLK, NT, SMEM_BYTES>>>(
        x, W0w, W0b, W1w, W1b, W2w, W2b, Wih1, b1, Wih2, b2, Wih3, b3,
        V1w, V1b, V2w, V2b, V3w, V3b, itn, (float*)d_out);
}